// round 8
// baseline (speedup 1.0000x reference)
#include <cuda_runtime.h>
#include <cstdint>

#define T 4096
#define H 4096
#define K 8
#define E 64
#define TK (T*K)            // 32768 slots
#define SORTB 64            // sort blocks (blocks 0..63), 512 slots each
#define NTOT (T + SORTB)    // total grid
#define ROWBYTES (H*4)      // 16384 bytes per row

// Scratch (no cudaMalloc allowed)
__device__ int g_rank[TK];            // stable rank within (sortblock, expert)
__device__ int g_blockcount[SORTB*E];
__device__ int g_blockbase[SORTB*E];
__device__ int g_expertbase[E];
__device__ int g_arrive;              // monotonic across replays; use &63
__device__ int g_done;                // monotonic across replays; use %NTOT
__device__ int g_flag;                // 0 at launch start; 1 = sort done; reset by last block

__device__ __forceinline__ uint32_t smem_u32(const void* p) {
    uint32_t a;
    asm("{ .reg .u64 t; cvta.to.shared.u64 t, %1; cvt.u32.u64 %0, t; }" : "=r"(a) : "l"(p));
    return a;
}

// ---------------------------------------------------------------------------
// One fused kernel.
// Blocks [0,64): counting sort (512 slots, 3 barriers); last-arriving block
// does cross-block/cross-expert scans, raises g_flag.
// Blocks [64,4160): one token each. cp.async.bulk G2S pulls the 16KB row into
// smem; combined row via LDS+scale+STG.cs; after the flag, ONE thread issues
// 8x 16KB cp.async.bulk S2G — the TMA engine streams the 512MB dispatched
// payload, decoupling store throughput from warp residency.
// ---------------------------------------------------------------------------
__global__ void __launch_bounds__(256) k_fused(const float* __restrict__ x,
                                               const float* __restrict__ wts,
                                               const int*   __restrict__ idx,
                                               float4* __restrict__ comb4,
                                               float*  __restrict__ disp,
                                               float*  __restrict__ tpe) {
    const int tid = threadIdx.x;

    if (blockIdx.x < SORTB) {
        // ================= SORT ROLE =================
        __shared__ int whist[16 * E];  // warps 0-7: chunk0, warps 8-15: chunk1
        __shared__ int s_last;
        const int b    = blockIdx.x;
        const int w    = tid >> 5;
        const int lane = tid & 31;

        #pragma unroll
        for (int i = 0; i < 4; i++) whist[tid + i * 256] = 0;
        __syncthreads();

        const int s0 = b * 512 + tid;
        const int s1 = s0 + 256;
        const int e0 = __ldg(&idx[s0]);
        const int e1 = __ldg(&idx[s1]);

        const unsigned m0 = __match_any_sync(0xffffffffu, e0);
        const int riw0 = __popc(m0 & ((1u << lane) - 1u));
        if ((__ffs(m0) - 1) == lane) whist[w * E + e0] = __popc(m0);
        const unsigned m1 = __match_any_sync(0xffffffffu, e1);
        const int riw1 = __popc(m1 & ((1u << lane) - 1u));
        if ((__ffs(m1) - 1) == lane) whist[(w + 8) * E + e1] = __popc(m1);
        __syncthreads();

        if (tid < E) {                 // scan 16 warp counts (chunk0 first = stable)
            int run = 0;
            #pragma unroll
            for (int ww = 0; ww < 16; ww++) {
                const int c = whist[ww * E + tid];
                whist[ww * E + tid] = run;
                run += c;
            }
            g_blockcount[b * E + tid] = run;
        }
        __syncthreads();

        g_rank[s0] = whist[w * E + e0] + riw0;
        g_rank[s1] = whist[(w + 8) * E + e1] + riw1;

        __threadfence();
        if (tid == 0) {
            const int ticket = atomicAdd(&g_arrive, 1);
            s_last = ((ticket & (SORTB - 1)) == (SORTB - 1));
        }
        __syncthreads();

        if (s_last) {
            __threadfence();
            __shared__ int tot[E];
            __shared__ int base[E];
            if (tid < E) {
                int run = 0;
                #pragma unroll
                for (int bb = 0; bb < SORTB; bb++) {
                    const int c = g_blockcount[bb * E + tid];
                    g_blockbase[bb * E + tid] = run;
                    run += c;
                }
                tot[tid] = run;
            }
            __syncthreads();
            if (tid == 0) {
                int acc = 0;
                #pragma unroll
                for (int i = 0; i < E; i++) { base[i] = acc; acc += tot[i]; }
            }
            __syncthreads();
            if (tid < E) {
                g_expertbase[tid] = base[tid];
                if (tpe) tpe[tid] = (float)tot[tid];
            }
            __threadfence();
            if (tid == 0) atomicExch(&g_flag, 1);
        }
    } else {
        // ================= TOKEN ROLE =================
        const int t = blockIdx.x - SORTB;
        __shared__ __align__(128) float4 stash[H / 4];   // 16 KB row buffer
        __shared__ __align__(8)  uint64_t mbar;

        const uint32_t stash_a = smem_u32(stash);
        const uint32_t mbar_a  = smem_u32(&mbar);

        if (tid == 0) {
            asm volatile("mbarrier.init.shared.b64 [%0], 1;" :: "r"(mbar_a) : "memory");
        }
        __syncthreads();
        if (tid == 0) {
            asm volatile("mbarrier.arrive.expect_tx.shared.b64 _, [%0], %1;"
                         :: "r"(mbar_a), "r"(ROWBYTES) : "memory");
            asm volatile("cp.async.bulk.shared::cluster.global.mbarrier::complete_tx::bytes "
                         "[%0], [%1], %2, [%3];"
                         :: "r"(stash_a), "l"(x + (size_t)t * H), "r"(ROWBYTES), "r"(mbar_a)
                         : "memory");
        }

        // Sort-independent scalar loads while the bulk copy is in flight.
        float ws = 0.f;
        #pragma unroll
        for (int k = 0; k < K; k++) ws += __ldg(&wts[t * K + k]);

        // Wait for the row to land in smem.
        {
            uint32_t done;
            asm volatile("{\n\t.reg .pred p;\n\t"
                         "mbarrier.try_wait.parity.acquire.cta.shared::cta.b64 p, [%1], 0;\n\t"
                         "selp.b32 %0, 1, 0, p;\n\t}"
                         : "=r"(done) : "r"(mbar_a) : "memory");
            while (!done) {
                asm volatile("{\n\t.reg .pred p;\n\t"
                             "mbarrier.try_wait.parity.acquire.cta.shared::cta.b64 p, [%1], 0, 0x989680;\n\t"
                             "selp.b32 %0, 1, 0, p;\n\t}"
                             : "=r"(done) : "r"(mbar_a) : "memory");
            }
        }

        // Combined row: LDS + scale + streaming STG.
        if (comb4) {
            #pragma unroll
            for (int i = 0; i < 4; i++) {
                float4 v = stash[tid + i * 256];
                float4 o = make_float4(v.x * ws, v.y * ws, v.z * ws, v.w * ws);
                __stcs(&comb4[(size_t)t * (H / 4) + tid + i * 256], o);
            }
        }

        if (disp) {
            // Wait for sort completion.
            if (tid == 0) {
                while (*((volatile int*)&g_flag) == 0) __nanosleep(64);
            }
            __syncthreads();
            __threadfence();

            if (tid == 0) {
                asm volatile("fence.proxy.async.shared::cta;" ::: "memory");
                #pragma unroll
                for (int k = 0; k < K; k++) {
                    const int s  = t * K + k;
                    const int bb = s >> 9;             // 512 slots per sort block
                    const int e  = idx[s];
                    const int d  = g_expertbase[e] + g_blockbase[bb * E + e] + g_rank[s];
                    asm volatile("cp.async.bulk.global.shared::cta.bulk_group [%0], [%1], %2;"
                                 :: "l"(disp + (size_t)d * H), "r"(stash_a), "r"(ROWBYTES)
                                 : "memory");
                }
                asm volatile("cp.async.bulk.commit_group;" ::: "memory");
                asm volatile("cp.async.bulk.wait_group 0;" ::: "memory");
            }
        }
    }

    // Epilogue: globally-last block resets g_flag for the next graph replay.
    __syncthreads();
    if (threadIdx.x == 0) {
        __threadfence();
        int d = atomicAdd(&g_done, 1);
        if ((d % NTOT) == (NTOT - 1)) atomicExch(&g_flag, 0);
    }
}

// ---------------------------------------------------------------------------
extern "C" void kernel_launch(void* const* d_in, const int* in_sizes, int n_in,
                              void* d_out, int out_size) {
    const float* x   = (const float*)d_in[0];
    const int*   idx = (const int*)  d_in[1];
    const float* w   = (const float*)d_in[2];
    float* out = (float*)d_out;

    const long long TH  = (long long)T * H;          // 16,777,216
    const long long TKH = (long long)TK * H;         // 134,217,728
    const long long os  = (long long)out_size;

    float* comb = nullptr;
    float* disp = nullptr;
    float* tpe  = nullptr;

    if (os >= TH + TKH) {
        comb = out;
        disp = out + TH;
        if (os >= TH + TKH + E) tpe = out + TH + TKH;
    } else if (os == TKH) {
        disp = out;                                  // dispatched-only layout
    } else {
        comb = out;                                  // combined-only layout
    }

    k_fused<<<NTOT, 256>>>(x, w, idx, (float4*)comb, disp, tpe);
}